// round 1
// baseline (speedup 1.0000x reference)
#include <cuda_runtime.h>
#include <math.h>

#define D       2048
#define NROWS   65536
#define NDREAMS 4
#define KMEM    8
#define MCAND   12          // KMEM + NDREAMS

#define SIMS_BLOCKS 1024
#define MV_BLOCKS_PER_MAT 64   // Wq / Wg1: 64 blocks x 64 rows = 4096 rows

// ---------------- scratch (no allocations allowed) ----------------
__device__ float g_scores[NROWS];
__device__ float g_qv_pre[D];
__device__ float g_gate_pre[D];
__device__ float g_qws[D];
__device__ float g_v[D];
__device__ float g_spre[D];
__device__ float g_sraw[D];
__device__ float g_C[MCAND * D];
__device__ int   g_idx[KMEM];
__device__ float g_scalars[2];   // [0] = gate g, [1] = cb (bias term for logits)

__device__ __forceinline__ float warp_sum(float v) {
#pragma unroll
    for (int off = 16; off; off >>= 1) v += __shfl_down_sync(0xFFFFFFFFu, v, off);
    return v;
}

// ======================= K0: prep =======================
// blocks 0..3: dreams -> g_C rows 8..11 ; blocks 4..7: zero accumulators
__global__ __launch_bounds__(256) void k0_prep(const float* __restrict__ z,
                                               const float* __restrict__ noise) {
    int b = blockIdx.x, t = threadIdx.x;
    if (b < NDREAMS) {
        __shared__ float buf[D];
        __shared__ float red[8];
        float ss = 0.f;
#pragma unroll
        for (int k = 0; k < 8; ++k) {
            int j = t + 256 * k;
            float v = 0.7f * noise[b * D + j] + 0.3f * z[j];
            buf[j] = v;
            ss += v * v;
        }
        ss = warp_sum(ss);
        if ((t & 31) == 0) red[t >> 5] = ss;
        __syncthreads();
        if (t == 0) {
            float s = 0.f;
#pragma unroll
            for (int w = 0; w < 8; ++w) s += red[w];
            red[0] = s;
        }
        __syncthreads();
        float inv = 1.0f / fmaxf(sqrtf(red[0]), 1e-12f);
#pragma unroll
        for (int k = 0; k < 8; ++k) {
            int j = t + 256 * k;
            g_C[(KMEM + b) * D + j] = buf[j] * inv;
        }
    } else {
        int seg = b - NDREAMS;                       // 0..3
        for (int j = seg * 256 + t; j < 3 * D; j += 4 * 256) {
            if (j < D)            g_qv_pre[j] = 0.f;
            else if (j < 2 * D)   g_gate_pre[j - D] = 0.f;
            else                  g_spre[j - 2 * D] = 0.f;
        }
    }
}

// ======================= K1: fused big kernel =======================
// blocks [0, SIMS_BLOCKS)            : cosine scores over mem_bank (warp per row)
// blocks [SIMS_BLOCKS, +64)          : Wq matvec partials -> g_qv_pre (atomic)
// blocks [SIMS_BLOCKS+64, +128)      : Wg1 matvec partials -> g_gate_pre (atomic)
__global__ __launch_bounds__(256) void k1_fused(const float* __restrict__ z,
                                                const float* __restrict__ h,
                                                const float* __restrict__ mem,
                                                const float* __restrict__ Wq,
                                                const float* __restrict__ Wg1) {
    int b = blockIdx.x;
    if (b < SIMS_BLOCKS) {
        const float4* z4 = (const float4*)z;
        int warp = threadIdx.x >> 5, lane = threadIdx.x & 31;
        for (int r = b * 8 + warp; r < NROWS; r += SIMS_BLOCKS * 8) {
            const float4* row4 = (const float4*)(mem + (size_t)r * D);
            float d0 = 0, d1 = 0, d2 = 0, d3 = 0;
            float n0 = 0, n1 = 0, n2 = 0, n3 = 0;
#pragma unroll
            for (int it = 0; it < 16; ++it) {
                float4 v  = row4[lane + 32 * it];
                float4 zz = z4[lane + 32 * it];
                d0 += v.x * zz.x; d1 += v.y * zz.y; d2 += v.z * zz.z; d3 += v.w * zz.w;
                n0 += v.x * v.x;  n1 += v.y * v.y;  n2 += v.z * v.z;  n3 += v.w * v.w;
            }
            float dot = (d0 + d1) + (d2 + d3);
            float nrm = (n0 + n1) + (n2 + n3);
            dot = warp_sum(dot);
            nrm = warp_sum(nrm);
            if (lane == 0) g_scores[r] = dot * rsqrtf(nrm);
        }
    } else {
        int mb = b - SIMS_BLOCKS;                        // 0..127
        const float* W   = (mb < MV_BLOCKS_PER_MAT) ? Wq : Wg1;
        float*       dst = (mb < MV_BLOCKS_PER_MAT) ? g_qv_pre : g_gate_pre;
        int rb = (mb & (MV_BLOCKS_PER_MAT - 1)) * 64;    // 64 rows per block
        int t = threadIdx.x;
        float acc[8];
#pragma unroll
        for (int k = 0; k < 8; ++k) acc[k] = 0.f;
        for (int i = 0; i < 64; ++i) {
            int row = rb + i;
            float x = (row < D) ? z[row] : h[row - D];
            const float* wr = W + (size_t)row * D;
#pragma unroll
            for (int k = 0; k < 8; ++k) acc[k] += x * wr[t + 256 * k];
        }
#pragma unroll
        for (int k = 0; k < 8; ++k) atomicAdd(&dst[t + 256 * k], acc[k]);
    }
}

// ======================= K2: top-8 + activations (single block, 1024 thr) ====
__global__ __launch_bounds__(1024) void k2_select(const float* __restrict__ bq,
                                                  const float* __restrict__ ws,
                                                  const float* __restrict__ bs,
                                                  const float* __restrict__ bc,
                                                  const float* __restrict__ bg1,
                                                  const float* __restrict__ wg2,
                                                  const float* __restrict__ bg2) {
    __shared__ float sv[1024];
    __shared__ int   si[1024];
    __shared__ float scb[32], sgp[32];
    int t = threadIdx.x;

    // 8 argmax passes (scores are L2-resident: 256 KB)
    for (int p = 0; p < KMEM; ++p) {
        float best = -INFINITY; int bi = 0;
        for (int j = t; j < NROWS; j += 1024) {
            float s = g_scores[j];
            if (s > best) { best = s; bi = j; }
        }
        sv[t] = best; si[t] = bi;
        __syncthreads();
        for (int off = 512; off; off >>= 1) {
            if (t < off && sv[t + off] > sv[t]) { sv[t] = sv[t + off]; si[t] = si[t + off]; }
            __syncthreads();
        }
        if (t == 0) {
            g_idx[p] = si[0];
            g_scores[si[0]] = -INFINITY;
        }
        __syncthreads();
    }

    // q_vec = tanh(qv_pre + bq); qws = q_vec * ws
    for (int j = t; j < D; j += 1024) {
        float qv = tanhf(g_qv_pre[j] + bq[j]);
        g_qws[j] = qv * ws[j];
    }
    __syncthreads();

    // cb = dot(bc, qws) + bs ; gate pre-sum = dot(tanh(gate_pre+bg1), wg2)
    float cbp = 0.f, gp = 0.f;
    for (int j = t; j < D; j += 1024) {
        cbp += bc[j] * g_qws[j];
        float hg = tanhf(g_gate_pre[j] + bg1[j]);
        gp += hg * wg2[j];
    }
    cbp = warp_sum(cbp);
    gp  = warp_sum(gp);
    if ((t & 31) == 0) { scb[t >> 5] = cbp; sgp[t >> 5] = gp; }
    __syncthreads();
    if (t == 0) {
        float c = 0.f, g = 0.f;
#pragma unroll
        for (int w = 0; w < 32; ++w) { c += scb[w]; g += sgp[w]; }
        g_scalars[1] = c + bs[0];
        g_scalars[0] = 1.0f / (1.0f + expf(-(g + bg2[0])));
    }
}

// ======================= K3: v = Wc @ qws  +  gather protos =======================
__global__ __launch_bounds__(256) void k3_v_gather(const float* __restrict__ mem,
                                                   const float* __restrict__ Wc) {
    int b = blockIdx.x;
    if (b < 128) {
        int warp = threadIdx.x >> 5, lane = threadIdx.x & 31;
        int gw = b * 8 + warp;
        const float4* q4 = (const float4*)g_qws;
        for (int i = gw; i < D; i += 1024) {
            const float4* wr = (const float4*)(Wc + (size_t)i * D);
            float a0 = 0, a1 = 0, a2 = 0, a3 = 0;
#pragma unroll
            for (int it = 0; it < 16; ++it) {
                float4 w = wr[lane + 32 * it];
                float4 q = q4[lane + 32 * it];
                a0 += w.x * q.x; a1 += w.y * q.y; a2 += w.z * q.z; a3 += w.w * q.w;
            }
            float s = warp_sum((a0 + a1) + (a2 + a3));
            if (lane == 0) g_v[i] = s;
        }
    } else {
        int m = b - 128;                         // 0..7
        int r = g_idx[m];
        const float4* src = (const float4*)(mem + (size_t)r * D);
        float4* dst = (float4*)(g_C + m * D);
        for (int j = threadIdx.x; j < D / 4; j += 256) dst[j] = src[j];
    }
}

// ======================= K4: logits -> softmax -> s_raw (single block) ========
__global__ __launch_bounds__(1024) void k4_attn() {
    __shared__ float wred[32][MCAND];
    __shared__ float attn[MCAND];
    int t = threadIdx.x, lane = t & 31, warp = t >> 5;

    float part[MCAND];
#pragma unroll
    for (int m = 0; m < MCAND; ++m) part[m] = 0.f;
    for (int j = t; j < D; j += 1024) {
        float vj = g_v[j];
#pragma unroll
        for (int m = 0; m < MCAND; ++m) part[m] += g_C[m * D + j] * vj;
    }
#pragma unroll
    for (int m = 0; m < MCAND; ++m) part[m] = warp_sum(part[m]);
    if (lane == 0) {
#pragma unroll
        for (int m = 0; m < MCAND; ++m) wred[warp][m] = part[m];
    }
    __syncthreads();
    if (t == 0) {
        float lg[MCAND]; float mx = -INFINITY;
#pragma unroll
        for (int m = 0; m < MCAND; ++m) {
            float s = g_scalars[1];
            for (int w = 0; w < 32; ++w) s += wred[w][m];
            lg[m] = s;
            mx = fmaxf(mx, s);
        }
        float den = 0.f;
#pragma unroll
        for (int m = 0; m < MCAND; ++m) { lg[m] = expf(lg[m] - mx); den += lg[m]; }
#pragma unroll
        for (int m = 0; m < MCAND; ++m) attn[m] = lg[m] / den;
    }
    __syncthreads();
    for (int j = t; j < D; j += 1024) {
        float s = 0.f;
#pragma unroll
        for (int m = 0; m < MCAND; ++m) s += attn[m] * g_C[m * D + j];
        g_sraw[j] = s;
    }
}

// ======================= K5: s_pre = s_raw @ Wm (split-K atomic) ===============
__global__ __launch_bounds__(256) void k5_wm(const float* __restrict__ Wm) {
    int b = blockIdx.x, t = threadIdx.x;
    int rb = b * 16;                              // 128 blocks x 16 rows
    float acc[8];
#pragma unroll
    for (int k = 0; k < 8; ++k) acc[k] = 0.f;
    for (int i = 0; i < 16; ++i) {
        float x = g_sraw[rb + i];
        const float* wr = Wm + (size_t)(rb + i) * D;
#pragma unroll
        for (int k = 0; k < 8; ++k) acc[k] += x * wr[t + 256 * k];
    }
#pragma unroll
    for (int k = 0; k < 8; ++k) atomicAdd(&g_spre[t + 256 * k], acc[k]);
}

// ======================= K6: output =======================
__global__ __launch_bounds__(256) void k6_out(const float* __restrict__ bm,
                                              float* __restrict__ out) {
    int j = blockIdx.x * 256 + threadIdx.x;
    out[j] = g_scalars[0] * tanhf(g_spre[j] + bm[j]);
}

// ======================= launch =======================
extern "C" void kernel_launch(void* const* d_in, const int* in_sizes, int n_in,
                              void* d_out, int out_size) {
    const float* z     = (const float*)d_in[0];
    const float* h     = (const float*)d_in[1];
    const float* mem   = (const float*)d_in[2];
    const float* noise = (const float*)d_in[3];
    const float* Wq    = (const float*)d_in[4];
    const float* bq    = (const float*)d_in[5];
    const float* Wc    = (const float*)d_in[6];
    const float* bc    = (const float*)d_in[7];
    const float* ws    = (const float*)d_in[8];
    const float* bs    = (const float*)d_in[9];
    const float* Wm    = (const float*)d_in[10];
    const float* bm    = (const float*)d_in[11];
    const float* Wg1   = (const float*)d_in[12];
    const float* bg1   = (const float*)d_in[13];
    const float* wg2   = (const float*)d_in[14];
    const float* bg2   = (const float*)d_in[15];
    float* out = (float*)d_out;

    k0_prep<<<8, 256>>>(z, noise);
    k1_fused<<<SIMS_BLOCKS + 2 * MV_BLOCKS_PER_MAT, 256>>>(z, h, mem, Wq, Wg1);
    k2_select<<<1, 1024>>>(bq, ws, bs, bc, bg1, wg2, bg2);
    k3_v_gather<<<128 + KMEM, 256>>>(mem, Wc);
    k4_attn<<<1, 1024>>>();
    k5_wm<<<128, 256>>>(Wm);
    k6_out<<<D / 256, 256>>>(bm, out);
}